// round 11
// baseline (speedup 1.0000x reference)
#include <cuda_runtime.h>
#include <cuda_fp16.h>
#include <math.h>
#include <stdint.h>

#define BATCH 2
#define NQL   4096
#define NKVL  4096
#define HID   256
#define NH    4
#define DH    64
#define MTOT  (BATCH * NQL)

// ---------------- scratch (device globals) ---------------------------------
__device__ __align__(16) __half g_Qh[BATCH * NH * NQL * DH];   // [bh][q][d], scaled by log2e/8
__device__ __align__(16) __half g_Kh[BATCH * NH * NKVL * DH];  // [bh][kv][d]
__device__ __align__(16) __half g_Vh[BATCH * NH * NKVL * DH];  // [bh][kv][d]
__device__ float g_AO[BATCH * NQL * HID];                      // attn out fp32

// ---------------- PTX helpers ----------------------------------------------
__device__ __forceinline__ uint32_t smem_u32(const void* p) {
    uint32_t a;
    asm("{ .reg .u64 t; cvta.to.shared.u64 t, %1; cvt.u32.u64 %0, t; }" : "=r"(a) : "l"(p));
    return a;
}
__device__ __forceinline__ void ldsm4(uint32_t& r0, uint32_t& r1, uint32_t& r2, uint32_t& r3, uint32_t a) {
    asm volatile("ldmatrix.sync.aligned.m8n8.x4.shared.b16 {%0,%1,%2,%3}, [%4];"
                 : "=r"(r0), "=r"(r1), "=r"(r2), "=r"(r3) : "r"(a));
}
__device__ __forceinline__ void ldsm4t(uint32_t& r0, uint32_t& r1, uint32_t& r2, uint32_t& r3, uint32_t a) {
    asm volatile("ldmatrix.sync.aligned.m8n8.x4.trans.shared.b16 {%0,%1,%2,%3}, [%4];"
                 : "=r"(r0), "=r"(r1), "=r"(r2), "=r"(r3) : "r"(a));
}
__device__ __forceinline__ void mma16816(float* c, const uint32_t* a, uint32_t b0, uint32_t b1) {
    asm volatile("mma.sync.aligned.m16n8k16.row.col.f32.f16.f16.f32 "
        "{%0,%1,%2,%3}, {%4,%5,%6,%7}, {%8,%9}, {%0,%1,%2,%3};"
        : "+f"(c[0]), "+f"(c[1]), "+f"(c[2]), "+f"(c[3])
        : "r"(a[0]), "r"(a[1]), "r"(a[2]), "r"(a[3]), "r"(b0), "r"(b1));
}
__device__ __forceinline__ uint32_t packh2(float x, float y) {
    __half2 h = __floats2half2_rn(x, y);
    return *(uint32_t*)&h;
}
__device__ __forceinline__ float ex2(float x) {
    float y;
    asm("ex2.approx.f32 %0, %1;" : "=f"(y) : "f"(x));
    return y;
}
#define CP16(dst, src)  asm volatile("cp.async.cg.shared.global [%0], [%1], 16;" :: "r"(dst), "l"(src))
#define CP_COMMIT()     asm volatile("cp.async.commit_group;" ::: "memory")
#define CP_WAIT0()      asm volatile("cp.async.wait_group 0;" ::: "memory")

#define LOG2E 1.4426950408889634f

// ---------------------------------------------------------------------------
// Projection GEMMs. k-chunk = 128 (2 iterations over HID=256).
// A tile [64 m][128 k] fp16, stride 136 (272B -> conflict-free ldmatrix).
// W tile [128 k][64 n] fp16, stride 72.
// ---------------------------------------------------------------------------
#define AST 136
#define GST 72

// stage A-block (64 rows x 128 f32 cols) -> fp16 smem (+ optional lo residual)
__device__ __forceinline__ void stage_A(const float* __restrict__ g, __half* s,
                                        int tid, __half* slo, int want_lo)
{
#pragma unroll
    for (int l = 0; l < 8; ++l) {
        int idx = tid + 128 * l;           // 0..1023
        int row = idx >> 4, cq = idx & 15;
        const float* ga = g + (size_t)row * HID + cq * 8;
        float4 x0 = *(const float4*)(ga);
        float4 x1 = *(const float4*)(ga + 4);
        __half2 h0 = __floats2half2_rn(x0.x, x0.y);
        __half2 h1 = __floats2half2_rn(x0.z, x0.w);
        __half2 h2 = __floats2half2_rn(x1.x, x1.y);
        __half2 h3 = __floats2half2_rn(x1.z, x1.w);
        *(uint4*)(s + row * AST + cq * 8) =
            make_uint4(*(uint32_t*)&h0, *(uint32_t*)&h1, *(uint32_t*)&h2, *(uint32_t*)&h3);
        if (want_lo) {
            __half2 l0 = __floats2half2_rn(x0.x - __low2float(h0),  x0.y - __high2float(h0));
            __half2 l1 = __floats2half2_rn(x0.z - __low2float(h1),  x0.w - __high2float(h1));
            __half2 l2 = __floats2half2_rn(x1.x - __low2float(h2),  x1.y - __high2float(h2));
            __half2 l3 = __floats2half2_rn(x1.z - __low2float(h3),  x1.w - __high2float(h3));
            *(uint4*)(slo + row * AST + cq * 8) =
                make_uint4(*(uint32_t*)&l0, *(uint32_t*)&l1, *(uint32_t*)&l2, *(uint32_t*)&l3);
        }
    }
}

// stage W-block (128 rows x 64 f32 cols) -> fp16 smem (+ optional lo residual)
__device__ __forceinline__ void stage_W(const float* __restrict__ g, __half* s,
                                        int tid, __half* slo, int want_lo)
{
#pragma unroll
    for (int l = 0; l < 8; ++l) {
        int idx = tid + 128 * l;           // 0..1023
        int row = idx >> 3, cq = idx & 7;
        const float* ga = g + (size_t)row * HID + cq * 8;
        float4 x0 = *(const float4*)(ga);
        float4 x1 = *(const float4*)(ga + 4);
        __half2 h0 = __floats2half2_rn(x0.x, x0.y);
        __half2 h1 = __floats2half2_rn(x0.z, x0.w);
        __half2 h2 = __floats2half2_rn(x1.x, x1.y);
        __half2 h3 = __floats2half2_rn(x1.z, x1.w);
        *(uint4*)(s + row * GST + cq * 8) =
            make_uint4(*(uint32_t*)&h0, *(uint32_t*)&h1, *(uint32_t*)&h2, *(uint32_t*)&h3);
        if (want_lo) {
            __half2 l0 = __floats2half2_rn(x0.x - __low2float(h0),  x0.y - __high2float(h0));
            __half2 l1 = __floats2half2_rn(x0.z - __low2float(h1),  x0.w - __high2float(h1));
            __half2 l2 = __floats2half2_rn(x1.x - __low2float(h2),  x1.y - __high2float(h2));
            __half2 l3 = __floats2half2_rn(x1.z - __low2float(h3),  x1.w - __high2float(h3));
            *(uint4*)(slo + row * GST + cq * 8) =
                make_uint4(*(uint32_t*)&l0, *(uint32_t*)&l1, *(uint32_t*)&l2, *(uint32_t*)&l3);
        }
    }
}

// one 64x64x128 accumulation pass: c += A_tile(warp m16) @ W_tile
__device__ __forceinline__ void hgemm_pass(const __half* sA, const __half* sW,
                                           float c[8][4], int lane, int m0r)
{
    const int r   = (lane & 7) + ((lane >> 3) & 1) * 8;
    const int cq  = (lane >> 4) * 8;
    const int wr  = (lane & 7) + (((lane >> 3) & 1) << 3);
    const int wc  = (lane >> 4) << 3;

    uint32_t a[8][4];
#pragma unroll
    for (int kc = 0; kc < 8; ++kc) {
        uint32_t ad = smem_u32(sA + (m0r + r) * AST + kc * 16 + cq);
        ldsm4(a[kc][0], a[kc][1], a[kc][2], a[kc][3], ad);
    }
#pragma unroll
    for (int dp = 0; dp < 4; ++dp) {
#pragma unroll
        for (int kc = 0; kc < 8; ++kc) {
            uint32_t b0, b1, b2, b3;
            uint32_t ad = smem_u32(sW + (kc * 16 + wr) * GST + dp * 16 + wc);
            ldsm4t(b0, b1, b2, b3, ad);
            mma16816(c[2 * dp],     a[kc], b0, b1);
            mma16816(c[2 * dp + 1], a[kc], b2, b3);
        }
    }
}

// dual pass (shared A-frags, two weights) for fused KV
__device__ __forceinline__ void hgemm_pass2(const __half* sA, const __half* sW1,
                                            const __half* sW2, float c1[8][4],
                                            float c2[8][4], int lane, int m0r)
{
    const int r   = (lane & 7) + ((lane >> 3) & 1) * 8;
    const int cq  = (lane >> 4) * 8;
    const int wr  = (lane & 7) + (((lane >> 3) & 1) << 3);
    const int wc  = (lane >> 4) << 3;

    uint32_t a[8][4];
#pragma unroll
    for (int kc = 0; kc < 8; ++kc) {
        uint32_t ad = smem_u32(sA + (m0r + r) * AST + kc * 16 + cq);
        ldsm4(a[kc][0], a[kc][1], a[kc][2], a[kc][3], ad);
    }
#pragma unroll
    for (int dp = 0; dp < 4; ++dp) {
#pragma unroll
        for (int kc = 0; kc < 8; ++kc) {
            uint32_t b0, b1, b2, b3;
            uint32_t ad1 = smem_u32(sW1 + (kc * 16 + wr) * GST + dp * 16 + wc);
            ldsm4t(b0, b1, b2, b3, ad1);
            mma16816(c1[2 * dp],     a[kc], b0, b1);
            mma16816(c1[2 * dp + 1], a[kc], b2, b3);
            uint32_t ad2 = smem_u32(sW2 + (kc * 16 + wr) * GST + dp * 16 + wc);
            ldsm4t(b0, b1, b2, b3, ad2);
            mma16816(c2[2 * dp],     a[kc], b0, b1);
            mma16816(c2[2 * dp + 1], a[kc], b2, b3);
        }
    }
}

#define A_HALVES (64 * AST)
#define W_HALVES (128 * GST)

__global__ __launch_bounds__(128) void hgemm_kernel(
    const float* __restrict__ A, const float* __restrict__ W,
    const float* __restrict__ bias, void* __restrict__ Cv,
    float alpha, int mode)
{
    extern __shared__ __half sh[];
    __half* sA   = sh;
    __half* sW   = sA + A_HALVES;
    __half* sAlo = sW + W_HALVES;          // mode 0 only
    __half* sWlo = sAlo + A_HALVES;

    const int tid  = threadIdx.x;
    const int warp = tid >> 5;
    const int lane = tid & 31;
    const int m0   = blockIdx.y * 64;
    const int n0   = blockIdx.x * 64;

    float c[8][4];
#pragma unroll
    for (int i = 0; i < 8; ++i)
#pragma unroll
        for (int j = 0; j < 4; ++j) c[i][j] = 0.0f;

#pragma unroll
    for (int k0 = 0; k0 < HID; k0 += 128) {
        stage_A(A + (size_t)m0 * HID + k0, sA, tid, sAlo, mode == 0);
        stage_W(W + (size_t)k0 * HID + n0, sW, tid, sWlo, mode == 0);
        __syncthreads();
        hgemm_pass(sA, sW, c, lane, warp * 16);
        if (mode == 0) {
            hgemm_pass(sAlo, sW, c, lane, warp * 16);
            hgemm_pass(sA, sWlo, c, lane, warp * 16);
        }
        __syncthreads();
    }

    const int g   = lane >> 2;
    const int tig = lane & 3;
    const int row0 = m0 + warp * 16 + g;
#pragma unroll
    for (int dt = 0; dt < 8; ++dt) {
        int col = 8 * dt + 2 * tig;
        float2 bv = *(const float2*)(bias + n0 + col);
        float v00 = (c[dt][0] + bv.x) * alpha;
        float v01 = (c[dt][1] + bv.y) * alpha;
        float v10 = (c[dt][2] + bv.x) * alpha;
        float v11 = (c[dt][3] + bv.y) * alpha;
        if (mode == 0) {
            float* C = (float*)Cv;
            *(float2*)(C + (size_t)row0 * HID + n0 + col)       = make_float2(v00, v01);
            *(float2*)(C + (size_t)(row0 + 8) * HID + n0 + col) = make_float2(v10, v11);
        } else {
            __half* C = (__half*)Cv;
            int h = n0 >> 6;
            {
                int b = row0 >> 12, rq = row0 & 4095;
                *(__half2*)(C + (((size_t)(b * NH + h) * NQL) + rq) * DH + col) =
                    __floats2half2_rn(v00, v01);
            }
            {
                int m1 = row0 + 8;
                int b = m1 >> 12, rq = m1 & 4095;
                *(__half2*)(C + (((size_t)(b * NH + h) * NQL) + rq) * DH + col) =
                    __floats2half2_rn(v10, v11);
            }
        }
    }
}

__global__ __launch_bounds__(128) void hgemm_kv_kernel(
    const float* __restrict__ A,
    const float* __restrict__ Wk, const float* __restrict__ bk,
    const float* __restrict__ Wv, const float* __restrict__ bv)
{
    extern __shared__ __half sh[];
    __half* sA  = sh;
    __half* sWk = sA + A_HALVES;
    __half* sWv = sWk + W_HALVES;

    const int tid  = threadIdx.x;
    const int warp = tid >> 5;
    const int lane = tid & 31;
    const int m0   = blockIdx.y * 64;
    const int n0   = blockIdx.x * 64;

    float ck[8][4], cv[8][4];
#pragma unroll
    for (int i = 0; i < 8; ++i)
#pragma unroll
        for (int j = 0; j < 4; ++j) { ck[i][j] = 0.0f; cv[i][j] = 0.0f; }

#pragma unroll
    for (int k0 = 0; k0 < HID; k0 += 128) {
        stage_A(A  + (size_t)m0 * HID + k0, sA,  tid, 0, 0);
        stage_W(Wk + (size_t)k0 * HID + n0, sWk, tid, 0, 0);
        stage_W(Wv + (size_t)k0 * HID + n0, sWv, tid, 0, 0);
        __syncthreads();
        hgemm_pass2(sA, sWk, sWv, ck, cv, lane, warp * 16);
        __syncthreads();
    }

    const int g   = lane >> 2;
    const int tig = lane & 3;
    const int row0 = m0 + warp * 16 + g;
    const int h = n0 >> 6;
#pragma unroll
    for (int dt = 0; dt < 8; ++dt) {
        int col = 8 * dt + 2 * tig;
        float2 bkv = *(const float2*)(bk + n0 + col);
        float2 bvv = *(const float2*)(bv + n0 + col);
        int b0i = row0 >> 12, rq0 = row0 & 4095;
        int m1 = row0 + 8;
        int b1i = m1 >> 12, rq1 = m1 & 4095;
        size_t o0 = (((size_t)(b0i * NH + h) * NKVL) + rq0) * DH + col;
        size_t o1 = (((size_t)(b1i * NH + h) * NKVL) + rq1) * DH + col;
        *(__half2*)(g_Kh + o0) = __floats2half2_rn(ck[dt][0] + bkv.x, ck[dt][1] + bkv.y);
        *(__half2*)(g_Kh + o1) = __floats2half2_rn(ck[dt][2] + bkv.x, ck[dt][3] + bkv.y);
        *(__half2*)(g_Vh + o0) = __floats2half2_rn(cv[dt][0] + bvv.x, cv[dt][1] + bvv.y);
        *(__half2*)(g_Vh + o1) = __floats2half2_rn(cv[dt][2] + bvv.x, cv[dt][3] + bvv.y);
    }
}

// ---------------------------------------------------------------------------
// HMMA flash attention, base-2 softmax (Q pre-scaled by log2e/8).
// CTA = 128 q rows, 4 warps, 32 rows (two m16 tiles) per warp.
// Mask enters as additive bias that INITIALIZES the S accumulators.
// ---------------------------------------------------------------------------
#define BM 128
#define BN 64
#define KST 72

__global__ __launch_bounds__(128, 3) void attn_hmma_kernel(const int* __restrict__ kv_mask)
{
    extern __shared__ __half smem_dyn[];
    __half* sQ    = smem_dyn;                 // [128][KST]
    __half* sK0   = sQ + BM * KST;            // [64][KST] x2
    __half* sV0   = sK0 + 2 * BN * KST;       // [64][KST] x2
    float*  smask = (float*)(sV0 + 2 * BN * KST);  // [2][64] additive bias

    const int tid  = threadIdx.x;
    const int warp = tid >> 5;
    const int lane = tid & 31;
    const int g    = lane >> 2;
    const int tig  = lane & 3;
    const int q0   = blockIdx.x * BM;
    const int bh   = blockIdx.y;
    const int b    = bh >> 2, h = bh & 3;
    const int m0   = warp * 32;

    const __half* Qg = g_Qh + ((size_t)bh * NQL + q0) * DH;
    const __half* Kg = g_Kh + (size_t)bh * NKVL * DH;
    const __half* Vg = g_Vh + (size_t)bh * NKVL * DH;
    const int*    Mg = kv_mask + b * NKVL;

    // ---- prologue ----
#pragma unroll
    for (int l = 0; l < 8; ++l) {
        int idx = tid + 128 * l;
        int row = idx >> 3, c = idx & 7;
        *(uint4*)(sQ + row * KST + c * 8) = *(const uint4*)(Qg + (size_t)row * DH + c * 8);
    }
#pragma unroll
    for (int l = 0; l < 4; ++l) {
        int idx = tid + 128 * l;
        int row = idx >> 3, c = idx & 7;
        CP16(smem_u32(sK0 + row * KST + c * 8), (const void*)(Kg + (size_t)row * DH + c * 8));
        CP16(smem_u32(sV0 + row * KST + c * 8), (const void*)(Vg + (size_t)row * DH + c * 8));
    }
    CP_COMMIT();
    if (tid < BN) smask[tid] = Mg[tid] ? 0.0f : -30000.0f;
    CP_WAIT0();
    __syncthreads();

    // ---- Q fragments for both m-tiles ----
    uint32_t qa[2][4][4];
    {
        int r = (lane & 7) + ((lane >> 3) & 1) * 8;
        int cq = (lane >> 4) * 8;
#pragma unroll
        for (int mt = 0; mt < 2; ++mt)
#pragma unroll
            for (int kc = 0; kc < 4; ++kc) {
                uint32_t a = smem_u32(sQ + (m0 + mt * 16 + r) * KST + kc * 16 + cq);
                ldsm4(qa[mt][kc][0], qa[mt][kc][1], qa[mt][kc][2], qa[mt][kc][3], a);
            }
    }

    float oc[2][8][4];
#pragma unroll
    for (int mt = 0; mt < 2; ++mt)
#pragma unroll
        for (int i = 0; i < 8; ++i)
#pragma unroll
            for (int j = 0; j < 4; ++j) oc[mt][i][j] = 0.0f;
    float lsum[2][2] = {{0.0f, 0.0f}, {0.0f, 0.0f}};

    const int krow = (lane & 7) + ((lane >> 4) << 3);
    const int kcol = ((lane >> 3) & 1) << 3;
    const int vrow = (lane & 7) + (((lane >> 3) & 1) << 3);
    const int vcol = (lane >> 4) << 3;

    const int NT = NKVL / BN;   // 64

    for (int t = 0; t < NT; ++t) {
        const int buf = t & 1;
        const __half* s_k = sK0 + buf * BN * KST;
        const __half* s_v = sV0 + buf * BN * KST;
        const float*  s_m = smask + buf * BN;

        float mnext = 0.0f;
        if (t + 1 < NT) {
            const __half* Kn = Kg + (size_t)(t + 1) * BN * DH;
            const __half* Vn = Vg + (size_t)(t + 1) * BN * DH;
            __half* dK = sK0 + (1 - buf) * BN * KST;
            __half* dV = sV0 + (1 - buf) * BN * KST;
#pragma unroll
            for (int l = 0; l < 4; ++l) {
                int idx = tid + 128 * l;
                int row = idx >> 3, c = idx & 7;
                CP16(smem_u32(dK + row * KST + c * 8), (const void*)(Kn + (size_t)row * DH + c * 8));
                CP16(smem_u32(dV + row * KST + c * 8), (const void*)(Vn + (size_t)row * DH + c * 8));
            }
            CP_COMMIT();
            if (tid < BN) mnext = Mg[(t + 1) * BN + tid] ? 0.0f : -30000.0f;
        }

#pragma unroll
        for (int np = 0; np < 4; ++np) {
            const int n0 = 16 * np;
            // mask bias -> S accumulator init
            float2 bA = *(const float2*)(s_m + n0 + 2 * tig);
            float2 bB = *(const float2*)(s_m + n0 + 8 + 2 * tig);
            float s[2][2][4];
#pragma unroll
            for (int mt = 0; mt < 2; ++mt) {
                s[mt][0][0] = bA.x; s[mt][0][1] = bA.y; s[mt][0][2] = bA.x; s[mt][0][3] = bA.y;
                s[mt][1][0] = bB.x; s[mt][1][1] = bB.y; s[mt][1][2] = bB.x; s[mt][1][3] = bB.y;
            }

#pragma unroll
            for (int kc = 0; kc < 4; ++kc) {
                uint32_t b0, b1, b2, b3;
                uint32_t a = smem_u32(s_k + (n0 + krow) * KST + kc * 16 + kcol);
                ldsm4(b0, b1, b2, b3, a);
                mma16816(s[0][0], qa[0][kc], b0, b1);
                mma16816(s[0][1], qa[0][kc], b2, b3);
                mma16816(s[1][0], qa[1][kc], b0, b1);
                mma16816(s[1][1], qa[1][kc], b2, b3);
            }

            uint32_t pa[2][4];
#pragma unroll
            for (int mt = 0; mt < 2; ++mt) {
                float p00 = ex2(s[mt][0][0]), p01 = ex2(s[mt][0][1]);
                float p02 = ex2(s[mt][0][2]), p03 = ex2(s[mt][0][3]);
                float p10 = ex2(s[mt][1][0]), p11 = ex2(s[mt][1][1]);
                float p12 = ex2(s[mt][1][2]), p13 = ex2(s[mt][1][3]);
                lsum[mt][0] += (p00 + p01) + (p10 + p11);
                lsum[mt][1] += (p02 + p03) + (p12 + p13);
                pa[mt][0] = packh2(p00, p01);
                pa[mt][1] = packh2(p02, p03);
                pa[mt][2] = packh2(p10, p11);
                pa[mt][3] = packh2(p12, p13);
            }

#pragma unroll
            for (int dp = 0; dp < 4; ++dp) {
                uint32_t b0, b1, b2, b3;
                uint32_t a = smem_u32(s_v + (n0 + vrow) * KST + dp * 16 + vcol);
                ldsm4t(b0, b1, b2, b3, a);
                mma16816(oc[0][2 * dp],     pa[0], b0, b1);
                mma16816(oc[0][2 * dp + 1], pa[0], b2, b3);
                mma16816(oc[1][2 * dp],     pa[1], b0, b1);
                mma16816(oc[1][2 * dp + 1], pa[1], b2, b3);
            }
        }

        if (t + 1 < NT && tid < BN) smask[(1 - buf) * BN + tid] = mnext;
        CP_WAIT0();
        __syncthreads();
    }

    // ---- quad-reduce row sums, normalize, store ----
#pragma unroll
    for (int mt = 0; mt < 2; ++mt) {
#pragma unroll
        for (int hh = 0; hh < 2; ++hh) {
            lsum[mt][hh] += __shfl_xor_sync(0xffffffffu, lsum[mt][hh], 1);
            lsum[mt][hh] += __shfl_xor_sync(0xffffffffu, lsum[mt][hh], 2);
        }
        float inv0 = (lsum[mt][0] > 0.0f) ? 1.0f / lsum[mt][0] : 0.0f;
        float inv1 = (lsum[mt][1] > 0.0f) ? 1.0f / lsum[mt][1] : 0.0f;
        const size_t row0 = (size_t)(b * NQL) + q0 + m0 + mt * 16 + g;
#pragma unroll
        for (int dt = 0; dt < 8; ++dt) {
            int col = h * DH + 8 * dt + 2 * tig;
            *(float2*)(g_AO + row0 * HID + col) =
                make_float2(oc[mt][dt][0] * inv0, oc[mt][dt][1] * inv0);
            *(float2*)(g_AO + (row0 + 8) * HID + col) =
                make_float2(oc[mt][dt][2] * inv1, oc[mt][dt][3] * inv1);
        }
    }
}

// ---------------------------------------------------------------------------
extern "C" void kernel_launch(void* const* d_in, const int* in_sizes, int n_in,
                              void* d_out, int out_size)
{
    const float* query     = (const float*)d_in[0];
    const float* key_value = (const float*)d_in[1];
    const int*   kv_mask   = (const int*)  d_in[2];
    const float* Wq = (const float*)d_in[3];
    const float* bq = (const float*)d_in[4];
    const float* Wk = (const float*)d_in[5];
    const float* bk = (const float*)d_in[6];
    const float* Wv = (const float*)d_in[7];
    const float* bv = (const float*)d_in[8];
    const float* Wo = (const float*)d_in[9];
    const float* bo = (const float*)d_in[10];

    void *Qp, *AOp;
    cudaGetSymbolAddress(&Qp,  g_Qh);
    cudaGetSymbolAddress(&AOp, g_AO);

    dim3 gblk(128);
    dim3 ggrid(HID / 64, MTOT / 64);   // (4, 128)

    const int smem_m1 = (A_HALVES + W_HALVES) * 2;          // 35840 B
    const int smem_m0 = smem_m1 * 2;                        // 71680 B
    const int smem_kv = (A_HALVES + 2 * W_HALVES) * 2;      // 54272 B

    cudaFuncSetAttribute(hgemm_kernel, cudaFuncAttributeMaxDynamicSharedMemorySize, smem_m0);
    cudaFuncSetAttribute(hgemm_kv_kernel, cudaFuncAttributeMaxDynamicSharedMemorySize, smem_kv);

    // Q pre-scaled by log2e / sqrt(DH) for base-2 softmax
    hgemm_kernel<<<ggrid, gblk, smem_m1>>>(query, Wq, bq, Qp, 0.125f * LOG2E, 1);
    hgemm_kv_kernel<<<ggrid, gblk, smem_kv>>>(key_value, Wk, bk, Wv, bv);

    const int attn_smem = (BM * KST + 4 * BN * KST) * 2 + 2 * BN * 4;  // 55808 B
    cudaFuncSetAttribute(attn_hmma_kernel, cudaFuncAttributeMaxDynamicSharedMemorySize, attn_smem);
    attn_hmma_kernel<<<dim3(NQL / BM, BATCH * NH), 128, attn_smem>>>(kv_mask);

    hgemm_kernel<<<ggrid, gblk, smem_m0>>>((const float*)AOp, Wo, bo, d_out, 1.0f, 0);
}

// round 12
// speedup vs baseline: 1.0859x; 1.0859x over previous
#include <cuda_runtime.h>
#include <cuda_fp16.h>
#include <math.h>
#include <stdint.h>

#define BATCH 2
#define NQL   4096
#define NKVL  4096
#define HID   256
#define NH    4
#define DH    64
#define MTOT  (BATCH * NQL)

// ---------------- scratch (device globals) ---------------------------------
__device__ __align__(16) __half g_Qh[BATCH * NH * NQL * DH];   // [bh][q][d], scaled by log2e/8
__device__ __align__(16) __half g_Kh[BATCH * NH * NKVL * DH];  // [bh][kv][d]
__device__ __align__(16) __half g_Vh[BATCH * NH * NKVL * DH];  // [bh][kv][d]
__device__ float g_AO[BATCH * NQL * HID];                      // attn out fp32

// ---------------- PTX helpers ----------------------------------------------
__device__ __forceinline__ uint32_t smem_u32(const void* p) {
    uint32_t a;
    asm("{ .reg .u64 t; cvta.to.shared.u64 t, %1; cvt.u32.u64 %0, t; }" : "=r"(a) : "l"(p));
    return a;
}
__device__ __forceinline__ void ldsm4(uint32_t& r0, uint32_t& r1, uint32_t& r2, uint32_t& r3, uint32_t a) {
    asm volatile("ldmatrix.sync.aligned.m8n8.x4.shared.b16 {%0,%1,%2,%3}, [%4];"
                 : "=r"(r0), "=r"(r1), "=r"(r2), "=r"(r3) : "r"(a));
}
__device__ __forceinline__ void ldsm4t(uint32_t& r0, uint32_t& r1, uint32_t& r2, uint32_t& r3, uint32_t a) {
    asm volatile("ldmatrix.sync.aligned.m8n8.x4.trans.shared.b16 {%0,%1,%2,%3}, [%4];"
                 : "=r"(r0), "=r"(r1), "=r"(r2), "=r"(r3) : "r"(a));
}
__device__ __forceinline__ void mma16816(float* c, const uint32_t* a, uint32_t b0, uint32_t b1) {
    asm volatile("mma.sync.aligned.m16n8k16.row.col.f32.f16.f16.f32 "
        "{%0,%1,%2,%3}, {%4,%5,%6,%7}, {%8,%9}, {%0,%1,%2,%3};"
        : "+f"(c[0]), "+f"(c[1]), "+f"(c[2]), "+f"(c[3])
        : "r"(a[0]), "r"(a[1]), "r"(a[2]), "r"(a[3]), "r"(b0), "r"(b1));
}
__device__ __forceinline__ uint32_t packh2(float x, float y) {
    __half2 h = __floats2half2_rn(x, y);
    return *(uint32_t*)&h;
}
__device__ __forceinline__ float ex2(float x) {
    float y;
    asm("ex2.approx.f32 %0, %1;" : "=f"(y) : "f"(x));
    return y;
}
#define CP16(dst, src)  asm volatile("cp.async.cg.shared.global [%0], [%1], 16;" :: "r"(dst), "l"(src))
#define CP_COMMIT()     asm volatile("cp.async.commit_group;" ::: "memory")
#define CP_WAIT0()      asm volatile("cp.async.wait_group 0;" ::: "memory")

#define LOG2E 1.4426950408889634f

// ---------------------------------------------------------------------------
// Projection GEMMs, k-chunk 64, register-prefetch double-buffered pipeline.
// Tiles [64][GST=72] fp16 in smem for both A (m x k) and W (k x n).
// ---------------------------------------------------------------------------
#define GST 72
#define TILE (64 * GST)

// load one 64x64 fp32 block (ld = HID) into 8 float4 regs
__device__ __forceinline__ void ldg8(const float* __restrict__ g, int tid, float4 r[8]) {
#pragma unroll
    for (int l = 0; l < 4; ++l) {
        int idx = tid + 128 * l;
        int row = idx >> 3, cq = idx & 7;
        const float* ga = g + (size_t)row * HID + cq * 8;
        r[2 * l]     = *(const float4*)(ga);
        r[2 * l + 1] = *(const float4*)(ga + 4);
    }
}

// convert prefetched regs -> fp16 tile (+ optional Markidis lo residual tile)
__device__ __forceinline__ void cvt_sts(const float4 r[8], __half* s, int tid,
                                        __half* slo, int want_lo) {
#pragma unroll
    for (int l = 0; l < 4; ++l) {
        int idx = tid + 128 * l;
        int row = idx >> 3, cq = idx & 7;
        float4 x0 = r[2 * l], x1 = r[2 * l + 1];
        __half2 h0 = __floats2half2_rn(x0.x, x0.y);
        __half2 h1 = __floats2half2_rn(x0.z, x0.w);
        __half2 h2 = __floats2half2_rn(x1.x, x1.y);
        __half2 h3 = __floats2half2_rn(x1.z, x1.w);
        *(uint4*)(s + row * GST + cq * 8) =
            make_uint4(*(uint32_t*)&h0, *(uint32_t*)&h1, *(uint32_t*)&h2, *(uint32_t*)&h3);
        if (want_lo) {
            __half2 l0 = __floats2half2_rn(x0.x - __low2float(h0),  x0.y - __high2float(h0));
            __half2 l1 = __floats2half2_rn(x0.z - __low2float(h1),  x0.w - __high2float(h1));
            __half2 l2 = __floats2half2_rn(x1.x - __low2float(h2),  x1.y - __high2float(h2));
            __half2 l3 = __floats2half2_rn(x1.z - __low2float(h3),  x1.w - __high2float(h3));
            *(uint4*)(slo + row * GST + cq * 8) =
                make_uint4(*(uint32_t*)&l0, *(uint32_t*)&l1, *(uint32_t*)&l2, *(uint32_t*)&l3);
        }
    }
}

// one 64x64x64 accumulation pass
__device__ __forceinline__ void hgemm_pass(const __half* sA, const __half* sW,
                                           float c[8][4], int lane, int m0r)
{
    const int r   = (lane & 7) + ((lane >> 3) & 1) * 8;
    const int cq  = (lane >> 4) * 8;
    const int wr  = (lane & 7) + (((lane >> 3) & 1) << 3);
    const int wc  = (lane >> 4) << 3;

    uint32_t a[4][4];
#pragma unroll
    for (int kc = 0; kc < 4; ++kc) {
        uint32_t ad = smem_u32(sA + (m0r + r) * GST + kc * 16 + cq);
        ldsm4(a[kc][0], a[kc][1], a[kc][2], a[kc][3], ad);
    }
#pragma unroll
    for (int dp = 0; dp < 4; ++dp) {
#pragma unroll
        for (int kc = 0; kc < 4; ++kc) {
            uint32_t b0, b1, b2, b3;
            uint32_t ad = smem_u32(sW + (kc * 16 + wr) * GST + dp * 16 + wc);
            ldsm4t(b0, b1, b2, b3, ad);
            mma16816(c[2 * dp],     a[kc], b0, b1);
            mma16816(c[2 * dp + 1], a[kc], b2, b3);
        }
    }
}

// ---- fused Q/K/V projection: grid.z selects which (all mode-1 fp16 scatter)
__global__ __launch_bounds__(128) void hgemm_qkv_kernel(
    const float* __restrict__ query, const float* __restrict__ key_value,
    const float* __restrict__ Wq, const float* __restrict__ bq,
    const float* __restrict__ Wk, const float* __restrict__ bk,
    const float* __restrict__ Wv, const float* __restrict__ bv)
{
    __shared__ __half sA[2][TILE];
    __shared__ __half sW[2][TILE];

    const int z = blockIdx.z;
    const float* A    = (z == 0) ? query : key_value;
    const float* W    = (z == 0) ? Wq : (z == 1) ? Wk : Wv;
    const float* bias = (z == 0) ? bq : (z == 1) ? bk : bv;
    __half* dst       = (z == 0) ? g_Qh : (z == 1) ? g_Kh : g_Vh;
    const float alpha = (z == 0) ? 0.125f * LOG2E : 1.0f;

    const int tid  = threadIdx.x;
    const int warp = tid >> 5;
    const int lane = tid & 31;
    const int m0   = blockIdx.y * 64;
    const int n0   = blockIdx.x * 64;

    float c[8][4];
#pragma unroll
    for (int i = 0; i < 8; ++i)
#pragma unroll
        for (int j = 0; j < 4; ++j) c[i][j] = 0.0f;

    float4 pa[8], pw[8];
    ldg8(A + (size_t)m0 * HID, tid, pa);
    ldg8(W + n0, tid, pw);
    cvt_sts(pa, sA[0], tid, 0, 0);
    cvt_sts(pw, sW[0], tid, 0, 0);
    __syncthreads();

#pragma unroll
    for (int kc = 0; kc < 4; ++kc) {
        const int buf = kc & 1;
        if (kc < 3) {
            ldg8(A + (size_t)m0 * HID + (kc + 1) * 64, tid, pa);
            ldg8(W + (size_t)(kc + 1) * 64 * HID + n0, tid, pw);
        }
        hgemm_pass(sA[buf], sW[buf], c, lane, warp * 16);
        if (kc < 3) {
            cvt_sts(pa, sA[1 - buf], tid, 0, 0);
            cvt_sts(pw, sW[1 - buf], tid, 0, 0);
        }
        __syncthreads();
    }

    const int g   = lane >> 2;
    const int tig = lane & 3;
    const int row0 = m0 + warp * 16 + g;
    const int h = n0 >> 6;
#pragma unroll
    for (int dt = 0; dt < 8; ++dt) {
        int col = 8 * dt + 2 * tig;
        float2 bv2 = *(const float2*)(bias + n0 + col);
        float v00 = (c[dt][0] + bv2.x) * alpha;
        float v01 = (c[dt][1] + bv2.y) * alpha;
        float v10 = (c[dt][2] + bv2.x) * alpha;
        float v11 = (c[dt][3] + bv2.y) * alpha;
        {
            int b = row0 >> 12, rq = row0 & 4095;
            *(__half2*)(dst + (((size_t)(b * NH + h) * NQL) + rq) * DH + col) =
                __floats2half2_rn(v00, v01);
        }
        {
            int m1 = row0 + 8;
            int b = m1 >> 12, rq = m1 & 4095;
            *(__half2*)(dst + (((size_t)(b * NH + h) * NQL) + rq) * DH + col) =
                __floats2half2_rn(v10, v11);
        }
    }
}

// ---- output projection: Markidis split (hi*hi + lo*hi + hi*lo), fp32 out
__global__ __launch_bounds__(128) void hgemm_o_kernel(
    const float* __restrict__ A, const float* __restrict__ W,
    const float* __restrict__ bias, float* __restrict__ C)
{
    extern __shared__ __half sh[];
    __half* sA   = sh;                  // [2][TILE]
    __half* sW   = sA  + 2 * TILE;
    __half* sAlo = sW  + 2 * TILE;
    __half* sWlo = sAlo + 2 * TILE;

    const int tid  = threadIdx.x;
    const int warp = tid >> 5;
    const int lane = tid & 31;
    const int m0   = blockIdx.y * 64;
    const int n0   = blockIdx.x * 64;

    float c[8][4];
#pragma unroll
    for (int i = 0; i < 8; ++i)
#pragma unroll
        for (int j = 0; j < 4; ++j) c[i][j] = 0.0f;

    float4 pa[8], pw[8];
    ldg8(A + (size_t)m0 * HID, tid, pa);
    ldg8(W + n0, tid, pw);
    cvt_sts(pa, sA, tid, sAlo, 1);
    cvt_sts(pw, sW, tid, sWlo, 1);
    __syncthreads();

#pragma unroll
    for (int kc = 0; kc < 4; ++kc) {
        const int buf = kc & 1;
        if (kc < 3) {
            ldg8(A + (size_t)m0 * HID + (kc + 1) * 64, tid, pa);
            ldg8(W + (size_t)(kc + 1) * 64 * HID + n0, tid, pw);
        }
        hgemm_pass(sA + buf * TILE, sW + buf * TILE, c, lane, warp * 16);
        hgemm_pass(sAlo + buf * TILE, sW + buf * TILE, c, lane, warp * 16);
        hgemm_pass(sA + buf * TILE, sWlo + buf * TILE, c, lane, warp * 16);
        if (kc < 3) {
            cvt_sts(pa, sA + (1 - buf) * TILE, tid, sAlo + (1 - buf) * TILE, 1);
            cvt_sts(pw, sW + (1 - buf) * TILE, tid, sWlo + (1 - buf) * TILE, 1);
        }
        __syncthreads();
    }

    const int g   = lane >> 2;
    const int tig = lane & 3;
    const int row0 = m0 + warp * 16 + g;
#pragma unroll
    for (int dt = 0; dt < 8; ++dt) {
        int col = 8 * dt + 2 * tig;
        float2 bv2 = *(const float2*)(bias + n0 + col);
        *(float2*)(C + (size_t)row0 * HID + n0 + col) =
            make_float2(c[dt][0] + bv2.x, c[dt][1] + bv2.y);
        *(float2*)(C + (size_t)(row0 + 8) * HID + n0 + col) =
            make_float2(c[dt][2] + bv2.x, c[dt][3] + bv2.y);
    }
}

// ---------------------------------------------------------------------------
// HMMA flash attention, base-2 softmax (Q pre-scaled by log2e/8).
// CTA = 128 q rows, 4 warps, 32 rows (two m16 tiles) per warp.
// Mask enters as additive bias that INITIALIZES the S accumulators.
// ---------------------------------------------------------------------------
#define BM 128
#define BN 64
#define KST 72

__global__ __launch_bounds__(128, 3) void attn_hmma_kernel(const int* __restrict__ kv_mask)
{
    extern __shared__ __half smem_dyn[];
    __half* sQ    = smem_dyn;                 // [128][KST]
    __half* sK0   = sQ + BM * KST;            // [64][KST] x2
    __half* sV0   = sK0 + 2 * BN * KST;       // [64][KST] x2
    float*  smask = (float*)(sV0 + 2 * BN * KST);  // [2][64] additive bias

    const int tid  = threadIdx.x;
    const int warp = tid >> 5;
    const int lane = tid & 31;
    const int g    = lane >> 2;
    const int tig  = lane & 3;
    const int q0   = blockIdx.x * BM;
    const int bh   = blockIdx.y;
    const int b    = bh >> 2, h = bh & 3;
    const int m0   = warp * 32;

    const __half* Qg = g_Qh + ((size_t)bh * NQL + q0) * DH;
    const __half* Kg = g_Kh + (size_t)bh * NKVL * DH;
    const __half* Vg = g_Vh + (size_t)bh * NKVL * DH;
    const int*    Mg = kv_mask + b * NKVL;

    // ---- prologue ----
#pragma unroll
    for (int l = 0; l < 8; ++l) {
        int idx = tid + 128 * l;
        int row = idx >> 3, c = idx & 7;
        *(uint4*)(sQ + row * KST + c * 8) = *(const uint4*)(Qg + (size_t)row * DH + c * 8);
    }
#pragma unroll
    for (int l = 0; l < 4; ++l) {
        int idx = tid + 128 * l;
        int row = idx >> 3, c = idx & 7;
        CP16(smem_u32(sK0 + row * KST + c * 8), (const void*)(Kg + (size_t)row * DH + c * 8));
        CP16(smem_u32(sV0 + row * KST + c * 8), (const void*)(Vg + (size_t)row * DH + c * 8));
    }
    CP_COMMIT();
    if (tid < BN) smask[tid] = Mg[tid] ? 0.0f : -30000.0f;
    CP_WAIT0();
    __syncthreads();

    // ---- Q fragments for both m-tiles ----
    uint32_t qa[2][4][4];
    {
        int r = (lane & 7) + ((lane >> 3) & 1) * 8;
        int cq = (lane >> 4) * 8;
#pragma unroll
        for (int mt = 0; mt < 2; ++mt)
#pragma unroll
            for (int kc = 0; kc < 4; ++kc) {
                uint32_t a = smem_u32(sQ + (m0 + mt * 16 + r) * KST + kc * 16 + cq);
                ldsm4(qa[mt][kc][0], qa[mt][kc][1], qa[mt][kc][2], qa[mt][kc][3], a);
            }
    }

    float oc[2][8][4];
#pragma unroll
    for (int mt = 0; mt < 2; ++mt)
#pragma unroll
        for (int i = 0; i < 8; ++i)
#pragma unroll
            for (int j = 0; j < 4; ++j) oc[mt][i][j] = 0.0f;
    float lsum[2][2] = {{0.0f, 0.0f}, {0.0f, 0.0f}};

    const int krow = (lane & 7) + ((lane >> 4) << 3);
    const int kcol = ((lane >> 3) & 1) << 3;
    const int vrow = (lane & 7) + (((lane >> 3) & 1) << 3);
    const int vcol = (lane >> 4) << 3;

    const int NT = NKVL / BN;   // 64

    for (int t = 0; t < NT; ++t) {
        const int buf = t & 1;
        const __half* s_k = sK0 + buf * BN * KST;
        const __half* s_v = sV0 + buf * BN * KST;
        const float*  s_m = smask + buf * BN;

        float mnext = 0.0f;
        if (t + 1 < NT) {
            const __half* Kn = Kg + (size_t)(t + 1) * BN * DH;
            const __half* Vn = Vg + (size_t)(t + 1) * BN * DH;
            __half* dK = sK0 + (1 - buf) * BN * KST;
            __half* dV = sV0 + (1 - buf) * BN * KST;
#pragma unroll
            for (int l = 0; l < 4; ++l) {
                int idx = tid + 128 * l;
                int row = idx >> 3, c = idx & 7;
                CP16(smem_u32(dK + row * KST + c * 8), (const void*)(Kn + (size_t)row * DH + c * 8));
                CP16(smem_u32(dV + row * KST + c * 8), (const void*)(Vn + (size_t)row * DH + c * 8));
            }
            CP_COMMIT();
            if (tid < BN) mnext = Mg[(t + 1) * BN + tid] ? 0.0f : -30000.0f;
        }

#pragma unroll
        for (int np = 0; np < 4; ++np) {
            const int n0 = 16 * np;
            float2 bA = *(const float2*)(s_m + n0 + 2 * tig);
            float2 bB = *(const float2*)(s_m + n0 + 8 + 2 * tig);
            float s[2][2][4];
#pragma unroll
            for (int mt = 0; mt < 2; ++mt) {
                s[mt][0][0] = bA.x; s[mt][0][1] = bA.y; s[mt][0][2] = bA.x; s[mt][0][3] = bA.y;
                s[mt][1][0] = bB.x; s[mt][1][1] = bB.y; s[mt][1][2] = bB.x; s[mt][1][3] = bB.y;
            }

#pragma unroll
            for (int kc = 0; kc < 4; ++kc) {
                uint32_t b0, b1, b2, b3;
                uint32_t a = smem_u32(s_k + (n0 + krow) * KST + kc * 16 + kcol);
                ldsm4(b0, b1, b2, b3, a);
                mma16816(s[0][0], qa[0][kc], b0, b1);
                mma16816(s[0][1], qa[0][kc], b2, b3);
                mma16816(s[1][0], qa[1][kc], b0, b1);
                mma16816(s[1][1], qa[1][kc], b2, b3);
            }

            uint32_t pa[2][4];
#pragma unroll
            for (int mt = 0; mt < 2; ++mt) {
                float p00 = ex2(s[mt][0][0]), p01 = ex2(s[mt][0][1]);
                float p02 = ex2(s[mt][0][2]), p03 = ex2(s[mt][0][3]);
                float p10 = ex2(s[mt][1][0]), p11 = ex2(s[mt][1][1]);
                float p12 = ex2(s[mt][1][2]), p13 = ex2(s[mt][1][3]);
                lsum[mt][0] += (p00 + p01) + (p10 + p11);
                lsum[mt][1] += (p02 + p03) + (p12 + p13);
                pa[mt][0] = packh2(p00, p01);
                pa[mt][1] = packh2(p02, p03);
                pa[mt][2] = packh2(p10, p11);
                pa[mt][3] = packh2(p12, p13);
            }

#pragma unroll
            for (int dp = 0; dp < 4; ++dp) {
                uint32_t b0, b1, b2, b3;
                uint32_t a = smem_u32(s_v + (n0 + vrow) * KST + dp * 16 + vcol);
                ldsm4t(b0, b1, b2, b3, a);
                mma16816(oc[0][2 * dp],     pa[0], b0, b1);
                mma16816(oc[0][2 * dp + 1], pa[0], b2, b3);
                mma16816(oc[1][2 * dp],     pa[1], b0, b1);
                mma16816(oc[1][2 * dp + 1], pa[1], b2, b3);
            }
        }

        if (t + 1 < NT && tid < BN) smask[(1 - buf) * BN + tid] = mnext;
        CP_WAIT0();
        __syncthreads();
    }

    // ---- quad-reduce row sums, normalize, store ----
#pragma unroll
    for (int mt = 0; mt < 2; ++mt) {
#pragma unroll
        for (int hh = 0; hh < 2; ++hh) {
            lsum[mt][hh] += __shfl_xor_sync(0xffffffffu, lsum[mt][hh], 1);
            lsum[mt][hh] += __shfl_xor_sync(0xffffffffu, lsum[mt][hh], 2);
        }
        float inv0 = (lsum[mt][0] > 0.0f) ? 1.0f / lsum[mt][0] : 0.0f;
        float inv1 = (lsum[mt][1] > 0.0f) ? 1.0f / lsum[mt][1] : 0.0f;
        const size_t row0 = (size_t)(b * NQL) + q0 + m0 + mt * 16 + g;
#pragma unroll
        for (int dt = 0; dt < 8; ++dt) {
            int col = h * DH + 8 * dt + 2 * tig;
            *(float2*)(g_AO + row0 * HID + col) =
                make_float2(oc[mt][dt][0] * inv0, oc[mt][dt][1] * inv0);
            *(float2*)(g_AO + (row0 + 8) * HID + col) =
                make_float2(oc[mt][dt][2] * inv1, oc[mt][dt][3] * inv1);
        }
    }
}

// ---------------------------------------------------------------------------
extern "C" void kernel_launch(void* const* d_in, const int* in_sizes, int n_in,
                              void* d_out, int out_size)
{
    const float* query     = (const float*)d_in[0];
    const float* key_value = (const float*)d_in[1];
    const int*   kv_mask   = (const int*)  d_in[2];
    const float* Wq = (const float*)d_in[3];
    const float* bq = (const float*)d_in[4];
    const float* Wk = (const float*)d_in[5];
    const float* bk = (const float*)d_in[6];
    const float* Wv = (const float*)d_in[7];
    const float* bv = (const float*)d_in[8];
    const float* Wo = (const float*)d_in[9];
    const float* bo = (const float*)d_in[10];

    void* AOp;
    cudaGetSymbolAddress(&AOp, g_AO);

    // fused Q/K/V projection: one launch, grid.z selects target
    hgemm_qkv_kernel<<<dim3(HID / 64, MTOT / 64, 3), 128>>>(
        query, key_value, Wq, bq, Wk, bk, Wv, bv);

    const int attn_smem = (BM * KST + 4 * BN * KST) * 2 + 2 * BN * 4;  // 55808 B
    cudaFuncSetAttribute(attn_hmma_kernel, cudaFuncAttributeMaxDynamicSharedMemorySize, attn_smem);
    attn_hmma_kernel<<<dim3(NQL / BM, BATCH * NH), 128, attn_smem>>>(kv_mask);

    const int smem_o = 8 * TILE * 2;   // 73728 B
    cudaFuncSetAttribute(hgemm_o_kernel, cudaFuncAttributeMaxDynamicSharedMemorySize, smem_o);
    hgemm_o_kernel<<<dim3(HID / 64, MTOT / 64), 128, smem_o>>>(
        (const float*)AOp, Wo, bo, (float*)d_out);
}

// round 14
// speedup vs baseline: 1.1890x; 1.0950x over previous
#include <cuda_runtime.h>
#include <cuda_fp16.h>
#include <math.h>
#include <stdint.h>

#define BATCH 2
#define NQL   4096
#define NKVL  4096
#define HID   256
#define NH    4
#define DH    64
#define MTOT  (BATCH * NQL)
#define KVSPLIT 4

// ---------------- scratch (device globals) ---------------------------------
__device__ __align__(16) __half g_Qh[BATCH * NH * NQL * DH];   // [bh][q][d], scaled log2e/8
__device__ __align__(16) __half g_Kh[BATCH * NH * NKVL * DH];  // [bh][kv][d]
__device__ __align__(16) __half g_Vh[BATCH * NH * NKVL * DH];  // [bh][kv][d]
__device__ float g_Op[KVSPLIT * BATCH * NH * NQL * DH];        // unnormalized O partials
__device__ float g_Lp[KVSPLIT * BATCH * NH * NQL];             // l partials
__device__ float g_AO[BATCH * NQL * HID];                      // attn out fp32

// ---------------- PTX helpers ----------------------------------------------
__device__ __forceinline__ uint32_t smem_u32(const void* p) {
    uint32_t a;
    asm("{ .reg .u64 t; cvta.to.shared.u64 t, %1; cvt.u32.u64 %0, t; }" : "=r"(a) : "l"(p));
    return a;
}
__device__ __forceinline__ void ldsm4(uint32_t& r0, uint32_t& r1, uint32_t& r2, uint32_t& r3, uint32_t a) {
    asm volatile("ldmatrix.sync.aligned.m8n8.x4.shared.b16 {%0,%1,%2,%3}, [%4];"
                 : "=r"(r0), "=r"(r1), "=r"(r2), "=r"(r3) : "r"(a));
}
__device__ __forceinline__ void ldsm4t(uint32_t& r0, uint32_t& r1, uint32_t& r2, uint32_t& r3, uint32_t a) {
    asm volatile("ldmatrix.sync.aligned.m8n8.x4.trans.shared.b16 {%0,%1,%2,%3}, [%4];"
                 : "=r"(r0), "=r"(r1), "=r"(r2), "=r"(r3) : "r"(a));
}
__device__ __forceinline__ void mma16816(float* c, const uint32_t* a, uint32_t b0, uint32_t b1) {
    asm volatile("mma.sync.aligned.m16n8k16.row.col.f32.f16.f16.f32 "
        "{%0,%1,%2,%3}, {%4,%5,%6,%7}, {%8,%9}, {%0,%1,%2,%3};"
        : "+f"(c[0]), "+f"(c[1]), "+f"(c[2]), "+f"(c[3])
        : "r"(a[0]), "r"(a[1]), "r"(a[2]), "r"(a[3]), "r"(b0), "r"(b1));
}
__device__ __forceinline__ uint32_t packh2(float x, float y) {
    __half2 h = __floats2half2_rn(x, y);
    return *(uint32_t*)&h;
}
__device__ __forceinline__ float ex2(float x) {
    float y;
    asm("ex2.approx.f32 %0, %1;" : "=f"(y) : "f"(x));
    return y;
}
#define CP16(dst, src)  asm volatile("cp.async.cg.shared.global [%0], [%1], 16;" :: "r"(dst), "l"(src))
#define CP_COMMIT()     asm volatile("cp.async.commit_group;" ::: "memory")
#define CP_WAIT0()      asm volatile("cp.async.wait_group 0;" ::: "memory")

#define LOG2E 1.4426950408889634f

// ---------------------------------------------------------------------------
// Projection GEMMs, k-chunk 64, register-prefetch double-buffered pipeline.
// ---------------------------------------------------------------------------
#define GST 72
#define TILE (64 * GST)

__device__ __forceinline__ void ldg8(const float* __restrict__ g, int tid, float4 r[8]) {
#pragma unroll
    for (int l = 0; l < 4; ++l) {
        int idx = tid + 128 * l;
        int row = idx >> 3, cq = idx & 7;
        const float* ga = g + (size_t)row * HID + cq * 8;
        r[2 * l]     = *(const float4*)(ga);
        r[2 * l + 1] = *(const float4*)(ga + 4);
    }
}

__device__ __forceinline__ void cvt_sts(const float4 r[8], __half* s, int tid,
                                        __half* slo, int want_lo) {
#pragma unroll
    for (int l = 0; l < 4; ++l) {
        int idx = tid + 128 * l;
        int row = idx >> 3, cq = idx & 7;
        float4 x0 = r[2 * l], x1 = r[2 * l + 1];
        __half2 h0 = __floats2half2_rn(x0.x, x0.y);
        __half2 h1 = __floats2half2_rn(x0.z, x0.w);
        __half2 h2 = __floats2half2_rn(x1.x, x1.y);
        __half2 h3 = __floats2half2_rn(x1.z, x1.w);
        *(uint4*)(s + row * GST + cq * 8) =
            make_uint4(*(uint32_t*)&h0, *(uint32_t*)&h1, *(uint32_t*)&h2, *(uint32_t*)&h3);
        if (want_lo) {
            __half2 l0 = __floats2half2_rn(x0.x - __low2float(h0),  x0.y - __high2float(h0));
            __half2 l1 = __floats2half2_rn(x0.z - __low2float(h1),  x0.w - __high2float(h1));
            __half2 l2 = __floats2half2_rn(x1.x - __low2float(h2),  x1.y - __high2float(h2));
            __half2 l3 = __floats2half2_rn(x1.z - __low2float(h3),  x1.w - __high2float(h3));
            *(uint4*)(slo + row * GST + cq * 8) =
                make_uint4(*(uint32_t*)&l0, *(uint32_t*)&l1, *(uint32_t*)&l2, *(uint32_t*)&l3);
        }
    }
}

__device__ __forceinline__ void hgemm_pass(const __half* sA, const __half* sW,
                                           float c[8][4], int lane, int m0r)
{
    const int r   = (lane & 7) + ((lane >> 3) & 1) * 8;
    const int cq  = (lane >> 4) * 8;
    const int wr  = (lane & 7) + (((lane >> 3) & 1) << 3);
    const int wc  = (lane >> 4) << 3;

    uint32_t a[4][4];
#pragma unroll
    for (int kc = 0; kc < 4; ++kc) {
        uint32_t ad = smem_u32(sA + (m0r + r) * GST + kc * 16 + cq);
        ldsm4(a[kc][0], a[kc][1], a[kc][2], a[kc][3], ad);
    }
#pragma unroll
    for (int dp = 0; dp < 4; ++dp) {
#pragma unroll
        for (int kc = 0; kc < 4; ++kc) {
            uint32_t b0, b1, b2, b3;
            uint32_t ad = smem_u32(sW + (kc * 16 + wr) * GST + dp * 16 + wc);
            ldsm4t(b0, b1, b2, b3, ad);
            mma16816(c[2 * dp],     a[kc], b0, b1);
            mma16816(c[2 * dp + 1], a[kc], b2, b3);
        }
    }
}

// ---- fused Q/K/V projection: grid.z selects which
__global__ __launch_bounds__(128) void hgemm_qkv_kernel(
    const float* __restrict__ query, const float* __restrict__ key_value,
    const float* __restrict__ Wq, const float* __restrict__ bq,
    const float* __restrict__ Wk, const float* __restrict__ bk,
    const float* __restrict__ Wv, const float* __restrict__ bv)
{
    __shared__ __half sA[2][TILE];
    __shared__ __half sW[2][TILE];

    const int z = blockIdx.z;
    const float* A    = (z == 0) ? query : key_value;
    const float* W    = (z == 0) ? Wq : (z == 1) ? Wk : Wv;
    const float* bias = (z == 0) ? bq : (z == 1) ? bk : bv;
    __half* dst       = (z == 0) ? g_Qh : (z == 1) ? g_Kh : g_Vh;
    const float alpha = (z == 0) ? 0.125f * LOG2E : 1.0f;

    const int tid  = threadIdx.x;
    const int warp = tid >> 5;
    const int lane = tid & 31;
    const int m0   = blockIdx.y * 64;
    const int n0   = blockIdx.x * 64;

    float c[8][4];
#pragma unroll
    for (int i = 0; i < 8; ++i)
#pragma unroll
        for (int j = 0; j < 4; ++j) c[i][j] = 0.0f;

    float4 pa[8], pw[8];
    ldg8(A + (size_t)m0 * HID, tid, pa);
    ldg8(W + n0, tid, pw);
    cvt_sts(pa, sA[0], tid, 0, 0);
    cvt_sts(pw, sW[0], tid, 0, 0);
    __syncthreads();

#pragma unroll
    for (int kc = 0; kc < 4; ++kc) {
        const int buf = kc & 1;
        if (kc < 3) {
            ldg8(A + (size_t)m0 * HID + (kc + 1) * 64, tid, pa);
            ldg8(W + (size_t)(kc + 1) * 64 * HID + n0, tid, pw);
        }
        hgemm_pass(sA[buf], sW[buf], c, lane, warp * 16);
        if (kc < 3) {
            cvt_sts(pa, sA[1 - buf], tid, 0, 0);
            cvt_sts(pw, sW[1 - buf], tid, 0, 0);
        }
        __syncthreads();
    }

    const int g   = lane >> 2;
    const int tig = lane & 3;
    const int row0 = m0 + warp * 16 + g;
    const int h = n0 >> 6;
#pragma unroll
    for (int dt = 0; dt < 8; ++dt) {
        int col = 8 * dt + 2 * tig;
        float2 bv2 = *(const float2*)(bias + n0 + col);
        float v00 = (c[dt][0] + bv2.x) * alpha;
        float v01 = (c[dt][1] + bv2.y) * alpha;
        float v10 = (c[dt][2] + bv2.x) * alpha;
        float v11 = (c[dt][3] + bv2.y) * alpha;
        {
            int b = row0 >> 12, rq = row0 & 4095;
            *(__half2*)(dst + (((size_t)(b * NH + h) * NQL) + rq) * DH + col) =
                __floats2half2_rn(v00, v01);
        }
        {
            int m1 = row0 + 8;
            int b = m1 >> 12, rq = m1 & 4095;
            *(__half2*)(dst + (((size_t)(b * NH + h) * NQL) + rq) * DH + col) =
                __floats2half2_rn(v10, v11);
        }
    }
}

// ---- output projection: 2-pass split (hi*Whi + hi*Wlo), fp32 out
__global__ __launch_bounds__(128) void hgemm_o_kernel(
    const float* __restrict__ A, const float* __restrict__ W,
    const float* __restrict__ bias, float* __restrict__ C)
{
    extern __shared__ __half sh[];
    __half* sA   = sh;                  // [2][TILE]
    __half* sW   = sA  + 2 * TILE;
    __half* sWlo = sW  + 2 * TILE;

    const int tid  = threadIdx.x;
    const int warp = tid >> 5;
    const int lane = tid & 31;
    const int m0   = blockIdx.y * 64;
    const int n0   = blockIdx.x * 64;

    float c[8][4];
#pragma unroll
    for (int i = 0; i < 8; ++i)
#pragma unroll
        for (int j = 0; j < 4; ++j) c[i][j] = 0.0f;

    float4 pa[8], pw[8];
    ldg8(A + (size_t)m0 * HID, tid, pa);
    ldg8(W + n0, tid, pw);
    cvt_sts(pa, sA, tid, 0, 0);
    cvt_sts(pw, sW, tid, sWlo, 1);
    __syncthreads();

#pragma unroll
    for (int kc = 0; kc < 4; ++kc) {
        const int buf = kc & 1;
        if (kc < 3) {
            ldg8(A + (size_t)m0 * HID + (kc + 1) * 64, tid, pa);
            ldg8(W + (size_t)(kc + 1) * 64 * HID + n0, tid, pw);
        }
        hgemm_pass(sA + buf * TILE, sW + buf * TILE, c, lane, warp * 16);
        hgemm_pass(sA + buf * TILE, sWlo + buf * TILE, c, lane, warp * 16);
        if (kc < 3) {
            cvt_sts(pa, sA + (1 - buf) * TILE, tid, 0, 0);
            cvt_sts(pw, sW + (1 - buf) * TILE, tid, sWlo + (1 - buf) * TILE, 1);
        }
        __syncthreads();
    }

    const int g   = lane >> 2;
    const int tig = lane & 3;
    const int row0 = m0 + warp * 16 + g;
#pragma unroll
    for (int dt = 0; dt < 8; ++dt) {
        int col = 8 * dt + 2 * tig;
        float2 bv2 = *(const float2*)(bias + n0 + col);
        *(float2*)(C + (size_t)row0 * HID + n0 + col) =
            make_float2(c[dt][0] + bv2.x, c[dt][1] + bv2.y);
        *(float2*)(C + (size_t)(row0 + 8) * HID + n0 + col) =
            make_float2(c[dt][2] + bv2.x, c[dt][3] + bv2.y);
    }
}

// ---------------------------------------------------------------------------
// HMMA flash attention, base-2 no-max softmax, KV-split partials.
// CTA = 256 q rows x 1/KVSPLIT of KV, 4 warps x 64 q-rows (4 m16 tiles).
// Each K/V ldmatrix feeds 8 MMAs. Partial O (unnormalized) + l written out.
// ---------------------------------------------------------------------------
#define BM 256
#define BN 64
#define KST 72
#define TPS (NKVL / BN / KVSPLIT)   /* tiles per split = 16 */

__global__ __launch_bounds__(128) void attn_hmma_kernel(const int* __restrict__ kv_mask)
{
    extern __shared__ __half smem_dyn[];
    __half* sQ    = smem_dyn;                 // [256][KST]
    __half* sK0   = sQ + BM * KST;            // [64][KST] x2
    __half* sV0   = sK0 + 2 * BN * KST;       // [64][KST] x2
    float*  smask = (float*)(sV0 + 2 * BN * KST);  // [2][64] additive bias

    const int tid  = threadIdx.x;
    const int warp = tid >> 5;
    const int lane = tid & 31;
    const int g    = lane >> 2;
    const int tig  = lane & 3;
    const int q0   = blockIdx.x * BM;
    const int bh   = blockIdx.y;
    const int spl  = blockIdx.z;
    const int b    = bh >> 2;
    const int m0   = warp * 64;
    const int t0   = spl * TPS;

    const __half* Qg = g_Qh + ((size_t)bh * NQL + q0) * DH;
    const __half* Kg = g_Kh + (size_t)bh * NKVL * DH;
    const __half* Vg = g_Vh + (size_t)bh * NKVL * DH;
    const int*    Mg = kv_mask + b * NKVL;

    // ---- prologue: stage Q (256 rows), first KV tile of split ----
#pragma unroll
    for (int l = 0; l < 16; ++l) {
        int idx = tid + 128 * l;
        int row = idx >> 3, c = idx & 7;
        *(uint4*)(sQ + row * KST + c * 8) = *(const uint4*)(Qg + (size_t)row * DH + c * 8);
    }
#pragma unroll
    for (int l = 0; l < 4; ++l) {
        int idx = tid + 128 * l;
        int row = idx >> 3, c = idx & 7;
        CP16(smem_u32(sK0 + row * KST + c * 8), (const void*)(Kg + (size_t)(t0 * BN + row) * DH + c * 8));
        CP16(smem_u32(sV0 + row * KST + c * 8), (const void*)(Vg + (size_t)(t0 * BN + row) * DH + c * 8));
    }
    CP_COMMIT();
    if (tid < BN) smask[tid] = Mg[t0 * BN + tid] ? 0.0f : -30000.0f;
    CP_WAIT0();
    __syncthreads();

    // ---- Q fragments for 4 m-tiles ----
    uint32_t qa[4][4][4];
    {
        int r = (lane & 7) + ((lane >> 3) & 1) * 8;
        int cq = (lane >> 4) * 8;
#pragma unroll
        for (int mt = 0; mt < 4; ++mt)
#pragma unroll
            for (int kc = 0; kc < 4; ++kc) {
                uint32_t a = smem_u32(sQ + (m0 + mt * 16 + r) * KST + kc * 16 + cq);
                ldsm4(qa[mt][kc][0], qa[mt][kc][1], qa[mt][kc][2], qa[mt][kc][3], a);
            }
    }

    float oc[4][8][4];
#pragma unroll
    for (int mt = 0; mt < 4; ++mt)
#pragma unroll
        for (int i = 0; i < 8; ++i)
#pragma unroll
            for (int j = 0; j < 4; ++j) oc[mt][i][j] = 0.0f;
    float lsum[4][2];
#pragma unroll
    for (int mt = 0; mt < 4; ++mt) { lsum[mt][0] = 0.0f; lsum[mt][1] = 0.0f; }

    const int krow = (lane & 7) + ((lane >> 4) << 3);
    const int kcol = ((lane >> 3) & 1) << 3;
    const int vrow = (lane & 7) + (((lane >> 3) & 1) << 3);
    const int vcol = (lane >> 4) << 3;

    for (int tt = 0; tt < TPS; ++tt) {
        const int t   = t0 + tt;
        const int buf = tt & 1;
        const __half* s_k = sK0 + buf * BN * KST;
        const __half* s_v = sV0 + buf * BN * KST;
        const float*  s_m = smask + buf * BN;

        float mnext = 0.0f;
        if (tt + 1 < TPS) {
            const __half* Kn = Kg + (size_t)(t + 1) * BN * DH;
            const __half* Vn = Vg + (size_t)(t + 1) * BN * DH;
            __half* dK = sK0 + (1 - buf) * BN * KST;
            __half* dV = sV0 + (1 - buf) * BN * KST;
#pragma unroll
            for (int l = 0; l < 4; ++l) {
                int idx = tid + 128 * l;
                int row = idx >> 3, c = idx & 7;
                CP16(smem_u32(dK + row * KST + c * 8), (const void*)(Kn + (size_t)row * DH + c * 8));
                CP16(smem_u32(dV + row * KST + c * 8), (const void*)(Vn + (size_t)row * DH + c * 8));
            }
            CP_COMMIT();
            if (tid < BN) mnext = Mg[(t + 1) * BN + tid] ? 0.0f : -30000.0f;
        }

#pragma unroll
        for (int np = 0; np < 4; ++np) {
            const int n0 = 16 * np;
            float2 bA = *(const float2*)(s_m + n0 + 2 * tig);
            float2 bB = *(const float2*)(s_m + n0 + 8 + 2 * tig);
            float s[4][2][4];
#pragma unroll
            for (int mt = 0; mt < 4; ++mt) {
                s[mt][0][0] = bA.x; s[mt][0][1] = bA.y; s[mt][0][2] = bA.x; s[mt][0][3] = bA.y;
                s[mt][1][0] = bB.x; s[mt][1][1] = bB.y; s[mt][1][2] = bB.x; s[mt][1][3] = bB.y;
            }

#pragma unroll
            for (int kc = 0; kc < 4; ++kc) {
                uint32_t b0, b1, b2, b3;
                uint32_t a = smem_u32(s_k + (n0 + krow) * KST + kc * 16 + kcol);
                ldsm4(b0, b1, b2, b3, a);
#pragma unroll
                for (int mt = 0; mt < 4; ++mt) {
                    mma16816(s[mt][0], qa[mt][kc], b0, b1);
                    mma16816(s[mt][1], qa[mt][kc], b2, b3);
                }
            }

            uint32_t pa[4][4];
#pragma unroll
            for (int mt = 0; mt < 4; ++mt) {
                float p00 = ex2(s[mt][0][0]), p01 = ex2(s[mt][0][1]);
                float p02 = ex2(s[mt][0][2]), p03 = ex2(s[mt][0][3]);
                float p10 = ex2(s[mt][1][0]), p11 = ex2(s[mt][1][1]);
                float p12 = ex2(s[mt][1][2]), p13 = ex2(s[mt][1][3]);
                lsum[mt][0] += (p00 + p01) + (p10 + p11);
                lsum[mt][1] += (p02 + p03) + (p12 + p13);
                pa[mt][0] = packh2(p00, p01);
                pa[mt][1] = packh2(p02, p03);
                pa[mt][2] = packh2(p10, p11);
                pa[mt][3] = packh2(p12, p13);
            }

#pragma unroll
            for (int dp = 0; dp < 4; ++dp) {
                uint32_t b0, b1, b2, b3;
                uint32_t a = smem_u32(s_v + (n0 + vrow) * KST + dp * 16 + vcol);
                ldsm4t(b0, b1, b2, b3, a);
#pragma unroll
                for (int mt = 0; mt < 4; ++mt) {
                    mma16816(oc[mt][2 * dp],     pa[mt], b0, b1);
                    mma16816(oc[mt][2 * dp + 1], pa[mt], b2, b3);
                }
            }
        }

        if (tt + 1 < TPS && tid < BN) smask[(1 - buf) * BN + tid] = mnext;
        CP_WAIT0();
        __syncthreads();
    }

    // ---- quad-reduce row sums; write UNNORMALIZED partials + l ----
    float* Op = g_Op + (((size_t)spl * (BATCH * NH) + bh) * NQL) * DH;
    float* Lp = g_Lp + ((size_t)spl * (BATCH * NH) + bh) * NQL;
#pragma unroll
    for (int mt = 0; mt < 4; ++mt) {
#pragma unroll
        for (int hh = 0; hh < 2; ++hh) {
            lsum[mt][hh] += __shfl_xor_sync(0xffffffffu, lsum[mt][hh], 1);
            lsum[mt][hh] += __shfl_xor_sync(0xffffffffu, lsum[mt][hh], 2);
        }
        const int row0 = q0 + m0 + mt * 16 + g;
        if (tig == 0) {
            Lp[row0]     = lsum[mt][0];
            Lp[row0 + 8] = lsum[mt][1];
        }
#pragma unroll
        for (int dt = 0; dt < 8; ++dt) {
            int col = 8 * dt + 2 * tig;
            *(float2*)(Op + (size_t)row0 * DH + col) =
                make_float2(oc[mt][dt][0], oc[mt][dt][1]);
            *(float2*)(Op + (size_t)(row0 + 8) * DH + col) =
                make_float2(oc[mt][dt][2], oc[mt][dt][3]);
        }
    }
}

// ---------------------------------------------------------------------------
// Reduce KV-split partials: AO[b][q][h*64+d] = sum_s Op / sum_s l
// ---------------------------------------------------------------------------
__global__ __launch_bounds__(256) void attn_reduce_kernel()
{
    int idx = blockIdx.x * 256 + threadIdx.x;       // (bh, q, dgroup of 4)
    int dg = idx & 15;
    int q  = (idx >> 4) & 4095;
    int bh = idx >> 16;

    const size_t rowoff = ((size_t)bh * NQL + q);
    float l = 0.0f;
    float4 v = make_float4(0.0f, 0.0f, 0.0f, 0.0f);
#pragma unroll
    for (int s = 0; s < KVSPLIT; ++s) {
        l += g_Lp[(size_t)s * (BATCH * NH) * NQL + rowoff];
        float4 p = *(const float4*)(g_Op + ((size_t)s * (BATCH * NH) * NQL + rowoff) * DH + dg * 4);
        v.x += p.x; v.y += p.y; v.z += p.z; v.w += p.w;
    }
    float inv = (l > 0.0f) ? 1.0f / l : 0.0f;
    int b = bh >> 2, h = bh & 3;
    *(float4*)(g_AO + ((size_t)(b * NQL + q)) * HID + h * DH + dg * 4) =
        make_float4(v.x * inv, v.y * inv, v.z * inv, v.w * inv);
}

// ---------------------------------------------------------------------------
extern "C" void kernel_launch(void* const* d_in, const int* in_sizes, int n_in,
                              void* d_out, int out_size)
{
    const float* query     = (const float*)d_in[0];
    const float* key_value = (const float*)d_in[1];
    const int*   kv_mask   = (const int*)  d_in[2];
    const float* Wq = (const float*)d_in[3];
    const float* bq = (const float*)d_in[4];
    const float* Wk = (const float*)d_in[5];
    const float* bk = (const float*)d_in[6];
    const float* Wv = (const float*)d_in[7];
    const float* bv = (const float*)d_in[8];
    const float* Wo = (const float*)d_in[9];
    const float* bo = (const float*)d_in[10];

    void* AOp;
    cudaGetSymbolAddress(&AOp, g_AO);

    // fused Q/K/V projection
    hgemm_qkv_kernel<<<dim3(HID / 64, MTOT / 64, 3), 128>>>(
        query, key_value, Wq, bq, Wk, bk, Wv, bv);

    // flash attention partials (KV-split)
    const int attn_smem = (BM * KST + 4 * BN * KST) * 2 + 2 * BN * 4;  // 74240 B
    cudaFuncSetAttribute(attn_hmma_kernel, cudaFuncAttributeMaxDynamicSharedMemorySize, attn_smem);
    attn_hmma_kernel<<<dim3(NQL / BM, BATCH * NH, KVSPLIT), 128, attn_smem>>>(kv_mask);

    // reduce partials -> g_AO
    attn_reduce_kernel<<<(BATCH * NH * NQL * 16) / 256, 256>>>();

    // output projection (2-pass split)
    const int smem_o = 6 * TILE * 2;   // 55296 B
    cudaFuncSetAttribute(hgemm_o_kernel, cudaFuncAttributeMaxDynamicSharedMemorySize, smem_o);
    hgemm_o_kernel<<<dim3(HID / 64, MTOT / 64), 128, smem_o>>>(
        (const float*)AOp, Wo, bo, (float*)d_out);
}

// round 15
// speedup vs baseline: 1.3135x; 1.1047x over previous
#include <cuda_runtime.h>
#include <cuda_fp16.h>
#include <math.h>
#include <stdint.h>

#define BATCH 2
#define NQL   4096
#define NKVL  4096
#define HID   256
#define NH    4
#define DH    64
#define MTOT  (BATCH * NQL)
#define KVSPLIT 4

// ---------------- scratch (device globals) ---------------------------------
__device__ __align__(16) __half g_Qh[BATCH * NH * NQL * DH];   // [bh][q][d], scaled log2e/8
__device__ __align__(16) __half g_Kh[BATCH * NH * NKVL * DH];  // [bh][kv][d]
__device__ __align__(16) __half g_Vh[BATCH * NH * NKVL * DH];  // [bh][kv][d]
__device__ float g_Op[KVSPLIT * BATCH * NH * NQL * DH];        // unnormalized O partials
__device__ float g_Lp[KVSPLIT * BATCH * NH * NQL];             // l partials
__device__ __align__(16) __half g_AOh[MTOT * HID];             // normalized attn out fp16
// fp16 weights (pre-converted once per launch)
__device__ __align__(16) __half g_Wqh[HID * HID];
__device__ __align__(16) __half g_Wkh[HID * HID];
__device__ __align__(16) __half g_Wvh[HID * HID];
__device__ __align__(16) __half g_Woh[HID * HID];
__device__ __align__(16) __half g_Wolo[HID * HID];             // Markidis residual of Wo

// ---------------- PTX helpers ----------------------------------------------
__device__ __forceinline__ uint32_t smem_u32(const void* p) {
    uint32_t a;
    asm("{ .reg .u64 t; cvta.to.shared.u64 t, %1; cvt.u32.u64 %0, t; }" : "=r"(a) : "l"(p));
    return a;
}
__device__ __forceinline__ void ldsm4(uint32_t& r0, uint32_t& r1, uint32_t& r2, uint32_t& r3, uint32_t a) {
    asm volatile("ldmatrix.sync.aligned.m8n8.x4.shared.b16 {%0,%1,%2,%3}, [%4];"
                 : "=r"(r0), "=r"(r1), "=r"(r2), "=r"(r3) : "r"(a));
}
__device__ __forceinline__ void ldsm4t(uint32_t& r0, uint32_t& r1, uint32_t& r2, uint32_t& r3, uint32_t a) {
    asm volatile("ldmatrix.sync.aligned.m8n8.x4.trans.shared.b16 {%0,%1,%2,%3}, [%4];"
                 : "=r"(r0), "=r"(r1), "=r"(r2), "=r"(r3) : "r"(a));
}
__device__ __forceinline__ void mma16816(float* c, const uint32_t* a, uint32_t b0, uint32_t b1) {
    asm volatile("mma.sync.aligned.m16n8k16.row.col.f32.f16.f16.f32 "
        "{%0,%1,%2,%3}, {%4,%5,%6,%7}, {%8,%9}, {%0,%1,%2,%3};"
        : "+f"(c[0]), "+f"(c[1]), "+f"(c[2]), "+f"(c[3])
        : "r"(a[0]), "r"(a[1]), "r"(a[2]), "r"(a[3]), "r"(b0), "r"(b1));
}
__device__ __forceinline__ uint32_t packh2(float x, float y) {
    __half2 h = __floats2half2_rn(x, y);
    return *(uint32_t*)&h;
}
__device__ __forceinline__ float ex2(float x) {
    float y;
    asm("ex2.approx.f32 %0, %1;" : "=f"(y) : "f"(x));
    return y;
}
#define CP16(dst, src)  asm volatile("cp.async.cg.shared.global [%0], [%1], 16;" :: "r"(dst), "l"(src))
#define CP_COMMIT()     asm volatile("cp.async.commit_group;" ::: "memory")
#define CP_WAIT0()      asm volatile("cp.async.wait_group 0;" ::: "memory")

#define LOG2E 1.4426950408889634f

// ---------------------------------------------------------------------------
// Weight pre-conversion: fp32 -> fp16 (+ residual for Wo)
// ---------------------------------------------------------------------------
__global__ __launch_bounds__(256) void wconv_kernel(
    const float* __restrict__ Wq, const float* __restrict__ Wk,
    const float* __restrict__ Wv, const float* __restrict__ Wo)
{
    int i = blockIdx.x * 256 + threadIdx.x;   // 65536 total
    g_Wqh[i] = __float2half(Wq[i]);
    g_Wkh[i] = __float2half(Wk[i]);
    g_Wvh[i] = __float2half(Wv[i]);
    float wo = Wo[i];
    __half h = __float2half(wo);
    g_Woh[i]  = h;
    g_Wolo[i] = __float2half(wo - __half2float(h));
}

// ---------------------------------------------------------------------------
// GEMM building blocks (64x64 tiles, stride 72)
// ---------------------------------------------------------------------------
#define GST 72
#define TILE (64 * GST)

__device__ __forceinline__ void ldg8(const float* __restrict__ g, int tid, float4 r[8]) {
#pragma unroll
    for (int l = 0; l < 4; ++l) {
        int idx = tid + 128 * l;
        int row = idx >> 3, cq = idx & 7;
        const float* ga = g + (size_t)row * HID + cq * 8;
        r[2 * l]     = *(const float4*)(ga);
        r[2 * l + 1] = *(const float4*)(ga + 4);
    }
}

__device__ __forceinline__ void cvt_sts(const float4 r[8], __half* s, int tid) {
#pragma unroll
    for (int l = 0; l < 4; ++l) {
        int idx = tid + 128 * l;
        int row = idx >> 3, cq = idx & 7;
        float4 x0 = r[2 * l], x1 = r[2 * l + 1];
        __half2 h0 = __floats2half2_rn(x0.x, x0.y);
        __half2 h1 = __floats2half2_rn(x0.z, x0.w);
        __half2 h2 = __floats2half2_rn(x1.x, x1.y);
        __half2 h3 = __floats2half2_rn(x1.z, x1.w);
        *(uint4*)(s + row * GST + cq * 8) =
            make_uint4(*(uint32_t*)&h0, *(uint32_t*)&h1, *(uint32_t*)&h2, *(uint32_t*)&h3);
    }
}

// async-stage a 64x64 fp16 tile (row stride HID halves in gmem)
__device__ __forceinline__ void stage_h16(const __half* __restrict__ g, __half* s, int tid) {
#pragma unroll
    for (int l = 0; l < 4; ++l) {
        int idx = tid + 128 * l;
        int row = idx >> 3, cq = idx & 7;
        CP16(smem_u32(s + row * GST + cq * 8), (const void*)(g + (size_t)row * HID + cq * 8));
    }
}

__device__ __forceinline__ void hgemm_pass(const __half* sA, const __half* sW,
                                           float c[8][4], int lane, int m0r)
{
    const int r   = (lane & 7) + ((lane >> 3) & 1) * 8;
    const int cq  = (lane >> 4) * 8;
    const int wr  = (lane & 7) + (((lane >> 3) & 1) << 3);
    const int wc  = (lane >> 4) << 3;

    uint32_t a[4][4];
#pragma unroll
    for (int kc = 0; kc < 4; ++kc) {
        uint32_t ad = smem_u32(sA + (m0r + r) * GST + kc * 16 + cq);
        ldsm4(a[kc][0], a[kc][1], a[kc][2], a[kc][3], ad);
    }
#pragma unroll
    for (int dp = 0; dp < 4; ++dp) {
#pragma unroll
        for (int kc = 0; kc < 4; ++kc) {
            uint32_t b0, b1, b2, b3;
            uint32_t ad = smem_u32(sW + (kc * 16 + wr) * GST + dp * 16 + wc);
            ldsm4t(b0, b1, b2, b3, ad);
            mma16816(c[2 * dp],     a[kc], b0, b1);
            mma16816(c[2 * dp + 1], a[kc], b2, b3);
        }
    }
}

// ---- fused Q/K/V projection: A fp32 (reg prefetch+cvt), W fp16 via cp.async
__global__ __launch_bounds__(128, 3) void hgemm_qkv_kernel(
    const float* __restrict__ query, const float* __restrict__ key_value,
    const float* __restrict__ bq, const float* __restrict__ bk,
    const float* __restrict__ bv)
{
    __shared__ __half sA[2][TILE];
    __shared__ __half sW[2][TILE];

    const int z = blockIdx.z;
    const float* A    = (z == 0) ? query : key_value;
    const __half* W   = (z == 0) ? g_Wqh : (z == 1) ? g_Wkh : g_Wvh;
    const float* bias = (z == 0) ? bq : (z == 1) ? bk : bv;
    __half* dst       = (z == 0) ? g_Qh : (z == 1) ? g_Kh : g_Vh;
    const float alpha = (z == 0) ? 0.125f * LOG2E : 1.0f;

    const int tid  = threadIdx.x;
    const int warp = tid >> 5;
    const int lane = tid & 31;
    const int m0   = blockIdx.y * 64;
    const int n0   = blockIdx.x * 64;

    float c[8][4];
#pragma unroll
    for (int i = 0; i < 8; ++i)
#pragma unroll
        for (int j = 0; j < 4; ++j) c[i][j] = 0.0f;

    float4 pa[8];
    ldg8(A + (size_t)m0 * HID, tid, pa);
    stage_h16(W + n0, sW[0], tid);
    CP_COMMIT();
    cvt_sts(pa, sA[0], tid);
    CP_WAIT0();
    __syncthreads();

#pragma unroll
    for (int kc = 0; kc < 4; ++kc) {
        const int buf = kc & 1;
        if (kc < 3) {
            ldg8(A + (size_t)m0 * HID + (kc + 1) * 64, tid, pa);
            stage_h16(W + (size_t)(kc + 1) * 64 * HID + n0, sW[1 - buf], tid);
            CP_COMMIT();
        }
        hgemm_pass(sA[buf], sW[buf], c, lane, warp * 16);
        if (kc < 3) cvt_sts(pa, sA[1 - buf], tid);
        CP_WAIT0();
        __syncthreads();
    }

    const int g   = lane >> 2;
    const int tig = lane & 3;
    const int row0 = m0 + warp * 16 + g;
    const int h = n0 >> 6;
#pragma unroll
    for (int dt = 0; dt < 8; ++dt) {
        int col = 8 * dt + 2 * tig;
        float2 bv2 = *(const float2*)(bias + n0 + col);
        float v00 = (c[dt][0] + bv2.x) * alpha;
        float v01 = (c[dt][1] + bv2.y) * alpha;
        float v10 = (c[dt][2] + bv2.x) * alpha;
        float v11 = (c[dt][3] + bv2.y) * alpha;
        {
            int b = row0 >> 12, rq = row0 & 4095;
            *(__half2*)(dst + (((size_t)(b * NH + h) * NQL) + rq) * DH + col) =
                __floats2half2_rn(v00, v01);
        }
        {
            int m1 = row0 + 8;
            int b = m1 >> 12, rq = m1 & 4095;
            *(__half2*)(dst + (((size_t)(b * NH + h) * NQL) + rq) * DH + col) =
                __floats2half2_rn(v10, v11);
        }
    }
}

// ---- output projection: everything fp16 via cp.async, 2-pass W split
__global__ __launch_bounds__(128, 3) void hgemm_o_kernel(
    const float* __restrict__ bias, float* __restrict__ C)
{
    extern __shared__ __half sh[];
    __half* sA   = sh;                  // [2][TILE]
    __half* sW   = sA  + 2 * TILE;
    __half* sWlo = sW  + 2 * TILE;

    const int tid  = threadIdx.x;
    const int warp = tid >> 5;
    const int lane = tid & 31;
    const int m0   = blockIdx.y * 64;
    const int n0   = blockIdx.x * 64;

    float c[8][4];
#pragma unroll
    for (int i = 0; i < 8; ++i)
#pragma unroll
        for (int j = 0; j < 4; ++j) c[i][j] = 0.0f;

    stage_h16(g_AOh + (size_t)m0 * HID, sA, tid);
    stage_h16(g_Woh + n0,  sW,   tid);
    stage_h16(g_Wolo + n0, sWlo, tid);
    CP_COMMIT();
    CP_WAIT0();
    __syncthreads();

#pragma unroll
    for (int kc = 0; kc < 4; ++kc) {
        const int buf = kc & 1;
        if (kc < 3) {
            stage_h16(g_AOh + (size_t)m0 * HID + (kc + 1) * 64, sA + (1 - buf) * TILE, tid);
            stage_h16(g_Woh + (size_t)(kc + 1) * 64 * HID + n0,  sW   + (1 - buf) * TILE, tid);
            stage_h16(g_Wolo + (size_t)(kc + 1) * 64 * HID + n0, sWlo + (1 - buf) * TILE, tid);
            CP_COMMIT();
        }
        hgemm_pass(sA + buf * TILE, sW + buf * TILE, c, lane, warp * 16);
        hgemm_pass(sA + buf * TILE, sWlo + buf * TILE, c, lane, warp * 16);
        CP_WAIT0();
        __syncthreads();
    }

    const int g   = lane >> 2;
    const int tig = lane & 3;
    const int row0 = m0 + warp * 16 + g;
#pragma unroll
    for (int dt = 0; dt < 8; ++dt) {
        int col = 8 * dt + 2 * tig;
        float2 bv2 = *(const float2*)(bias + n0 + col);
        *(float2*)(C + (size_t)row0 * HID + n0 + col) =
            make_float2(c[dt][0] + bv2.x, c[dt][1] + bv2.y);
        *(float2*)(C + (size_t)(row0 + 8) * HID + n0 + col) =
            make_float2(c[dt][2] + bv2.x, c[dt][3] + bv2.y);
    }
}

// ---------------------------------------------------------------------------
// HMMA flash attention, base-2 no-max softmax, KV-split partials.
// CTA = 128 q rows x 1/KVSPLIT of KV, 4 warps x 32 rows (2 m16 tiles).
// ---------------------------------------------------------------------------
#define BM 128
#define BN 64
#define KST 72
#define TPS (NKVL / BN / KVSPLIT)   /* 16 */

__global__ __launch_bounds__(128, 3) void attn_hmma_kernel(const int* __restrict__ kv_mask)
{
    extern __shared__ __half smem_dyn[];
    __half* sQ    = smem_dyn;                 // [128][KST]
    __half* sK0   = sQ + BM * KST;            // [64][KST] x2
    __half* sV0   = sK0 + 2 * BN * KST;       // [64][KST] x2
    float*  smask = (float*)(sV0 + 2 * BN * KST);  // [2][64] additive bias

    const int tid  = threadIdx.x;
    const int warp = tid >> 5;
    const int lane = tid & 31;
    const int g    = lane >> 2;
    const int tig  = lane & 3;
    const int q0   = blockIdx.x * BM;
    const int bh   = blockIdx.y;
    const int spl  = blockIdx.z;
    const int b    = bh >> 2;
    const int m0   = warp * 32;
    const int t0   = spl * TPS;

    const __half* Qg = g_Qh + ((size_t)bh * NQL + q0) * DH;
    const __half* Kg = g_Kh + (size_t)bh * NKVL * DH;
    const __half* Vg = g_Vh + (size_t)bh * NKVL * DH;
    const int*    Mg = kv_mask + b * NKVL;

    // ---- prologue: stage Q (128 rows), first KV tile of split ----
#pragma unroll
    for (int l = 0; l < 8; ++l) {
        int idx = tid + 128 * l;
        int row = idx >> 3, c = idx & 7;
        *(uint4*)(sQ + row * KST + c * 8) = *(const uint4*)(Qg + (size_t)row * DH + c * 8);
    }
#pragma unroll
    for (int l = 0; l < 4; ++l) {
        int idx = tid + 128 * l;
        int row = idx >> 3, c = idx & 7;
        CP16(smem_u32(sK0 + row * KST + c * 8), (const void*)(Kg + (size_t)(t0 * BN + row) * DH + c * 8));
        CP16(smem_u32(sV0 + row * KST + c * 8), (const void*)(Vg + (size_t)(t0 * BN + row) * DH + c * 8));
    }
    CP_COMMIT();
    if (tid < BN) smask[tid] = Mg[t0 * BN + tid] ? 0.0f : -30000.0f;
    CP_WAIT0();
    __syncthreads();

    // ---- Q fragments for 2 m-tiles ----
    uint32_t qa[2][4][4];
    {
        int r = (lane & 7) + ((lane >> 3) & 1) * 8;
        int cq = (lane >> 4) * 8;
#pragma unroll
        for (int mt = 0; mt < 2; ++mt)
#pragma unroll
            for (int kc = 0; kc < 4; ++kc) {
                uint32_t a = smem_u32(sQ + (m0 + mt * 16 + r) * KST + kc * 16 + cq);
                ldsm4(qa[mt][kc][0], qa[mt][kc][1], qa[mt][kc][2], qa[mt][kc][3], a);
            }
    }

    float oc[2][8][4];
#pragma unroll
    for (int mt = 0; mt < 2; ++mt)
#pragma unroll
        for (int i = 0; i < 8; ++i)
#pragma unroll
            for (int j = 0; j < 4; ++j) oc[mt][i][j] = 0.0f;
    float lsum[2][2] = {{0.0f, 0.0f}, {0.0f, 0.0f}};

    const int krow = (lane & 7) + ((lane >> 4) << 3);
    const int kcol = ((lane >> 3) & 1) << 3;
    const int vrow = (lane & 7) + (((lane >> 3) & 1) << 3);
    const int vcol = (lane >> 4) << 3;

    for (int tt = 0; tt < TPS; ++tt) {
        const int t   = t0 + tt;
        const int buf = tt & 1;
        const __half* s_k = sK0 + buf * BN * KST;
        const __half* s_v = sV0 + buf * BN * KST;
        const float*  s_m = smask + buf * BN;

        float mnext = 0.0f;
        if (tt + 1 < TPS) {
            const __half* Kn = Kg + (size_t)(t + 1) * BN * DH;
            const __half* Vn = Vg + (size_t)(t + 1) * BN * DH;
            __half* dK = sK0 + (1 - buf) * BN * KST;
            __half* dV = sV0 + (1 - buf) * BN * KST;
#pragma unroll
            for (int l = 0; l < 4; ++l) {
                int idx = tid + 128 * l;
                int row = idx >> 3, c = idx & 7;
                CP16(smem_u32(dK + row * KST + c * 8), (const void*)(Kn + (size_t)row * DH + c * 8));
                CP16(smem_u32(dV + row * KST + c * 8), (const void*)(Vn + (size_t)row * DH + c * 8));
            }
            CP_COMMIT();
            if (tid < BN) mnext = Mg[(t + 1) * BN + tid] ? 0.0f : -30000.0f;
        }

#pragma unroll
        for (int np = 0; np < 4; ++np) {
            const int n0 = 16 * np;
            float2 bA = *(const float2*)(s_m + n0 + 2 * tig);
            float2 bB = *(const float2*)(s_m + n0 + 8 + 2 * tig);
            float s[2][2][4];
#pragma unroll
            for (int mt = 0; mt < 2; ++mt) {
                s[mt][0][0] = bA.x; s[mt][0][1] = bA.y; s[mt][0][2] = bA.x; s[mt][0][3] = bA.y;
                s[mt][1][0] = bB.x; s[mt][1][1] = bB.y; s[mt][1][2] = bB.x; s[mt][1][3] = bB.y;
            }

#pragma unroll
            for (int kc = 0; kc < 4; ++kc) {
                uint32_t b0, b1, b2, b3;
                uint32_t a = smem_u32(s_k + (n0 + krow) * KST + kc * 16 + kcol);
                ldsm4(b0, b1, b2, b3, a);
                mma16816(s[0][0], qa[0][kc], b0, b1);
                mma16816(s[0][1], qa[0][kc], b2, b3);
                mma16816(s[1][0], qa[1][kc], b0, b1);
                mma16816(s[1][1], qa[1][kc], b2, b3);
            }

            uint32_t pa[2][4];
#pragma unroll
            for (int mt = 0; mt < 2; ++mt) {
                float p00 = ex2(s[mt][0][0]), p01 = ex2(s[mt][0][1]);
                float p02 = ex2(s[mt][0][2]), p03 = ex2(s[mt][0][3]);
                float p10 = ex2(s[mt][1][0]), p11 = ex2(s[mt][1][1]);
                float p12 = ex2(s[mt][1][2]), p13 = ex2(s[mt][1][3]);
                lsum[mt][0] += (p00 + p01) + (p10 + p11);
                lsum[mt][1] += (p02 + p03) + (p12 + p13);
                pa[mt][0] = packh2(p00, p01);
                pa[mt][1] = packh2(p02, p03);
                pa[mt][2] = packh2(p10, p11);
                pa[mt][3] = packh2(p12, p13);
            }

#pragma unroll
            for (int dp = 0; dp < 4; ++dp) {
                uint32_t b0, b1, b2, b3;
                uint32_t a = smem_u32(s_v + (n0 + vrow) * KST + dp * 16 + vcol);
                ldsm4t(b0, b1, b2, b3, a);
                mma16816(oc[0][2 * dp],     pa[0], b0, b1);
                mma16816(oc[0][2 * dp + 1], pa[0], b2, b3);
                mma16816(oc[1][2 * dp],     pa[1], b0, b1);
                mma16816(oc[1][2 * dp + 1], pa[1], b2, b3);
            }
        }

        if (tt + 1 < TPS && tid < BN) smask[(1 - buf) * BN + tid] = mnext;
        CP_WAIT0();
        __syncthreads();
    }

    // ---- quad-reduce row sums; write UNNORMALIZED partials + l ----
    float* Op = g_Op + (((size_t)spl * (BATCH * NH) + bh) * NQL) * DH;
    float* Lp = g_Lp + ((size_t)spl * (BATCH * NH) + bh) * NQL;
#pragma unroll
    for (int mt = 0; mt < 2; ++mt) {
#pragma unroll
        for (int hh = 0; hh < 2; ++hh) {
            lsum[mt][hh] += __shfl_xor_sync(0xffffffffu, lsum[mt][hh], 1);
            lsum[mt][hh] += __shfl_xor_sync(0xffffffffu, lsum[mt][hh], 2);
        }
        const int row0 = q0 + m0 + mt * 16 + g;
        if (tig == 0) {
            Lp[row0]     = lsum[mt][0];
            Lp[row0 + 8] = lsum[mt][1];
        }
#pragma unroll
        for (int dt = 0; dt < 8; ++dt) {
            int col = 8 * dt + 2 * tig;
            *(float2*)(Op + (size_t)row0 * DH + col) =
                make_float2(oc[mt][dt][0], oc[mt][dt][1]);
            *(float2*)(Op + (size_t)(row0 + 8) * DH + col) =
                make_float2(oc[mt][dt][2], oc[mt][dt][3]);
        }
    }
}

// ---------------------------------------------------------------------------
// Reduce KV-split partials -> fp16 AO[b][q][h*64+d]
// ---------------------------------------------------------------------------
__global__ __launch_bounds__(256) void attn_reduce_kernel()
{
    int idx = blockIdx.x * 256 + threadIdx.x;       // (bh, q, dgroup of 4)
    int dg = idx & 15;
    int q  = (idx >> 4) & 4095;
    int bh = idx >> 16;

    const size_t rowoff = ((size_t)bh * NQL + q);
    float l = 0.0f;
    float4 v = make_float4(0.0f, 0.0f, 0.0f, 0.0f);
#pragma unroll
    for (int s = 0; s < KVSPLIT; ++s) {
        l += g_Lp[(size_t)s * (BATCH * NH) * NQL + rowoff];
        float4 p = *(const float4*)(g_Op + ((size_t)s * (BATCH * NH) * NQL + rowoff) * DH + dg * 4);
        v.x += p.x; v.y += p.y; v.z += p.z; v.w += p.w;
    }
    float inv = (l > 0.0f) ? 1.0f / l : 0.0f;
    int b = bh >> 2, h = bh & 3;
    __half2 h0 = __floats2half2_rn(v.x * inv, v.y * inv);
    __half2 h1 = __floats2half2_rn(v.z * inv, v.w * inv);
    *(uint2*)(g_AOh + ((size_t)(b * NQL + q)) * HID + h * DH + dg * 4) =
        make_uint2(*(uint32_t*)&h0, *(uint32_t*)&h1);
}

// ---------------------------------------------------------------------------
extern "C" void kernel_launch(void* const* d_in, const int* in_sizes, int n_in,
                              void* d_out, int out_size)
{
    const float* query     = (const float*)d_in[0];
    const float* key_value = (const float*)d_in[1];
    const int*   kv_mask   = (const int*)  d_in[2];
    const float* Wq = (const float*)d_in[3];
    const float* bq = (const float*)d_in[4];
    const float* Wk = (const float*)d_in[5];
    const float* bk = (const float*)d_in[6];
    const float* Wv = (const float*)d_in[7];
    const float* bv = (const float*)d_in[8];
    const float* Wo = (const float*)d_in[9];
    const float* bo = (const float*)d_in[10];

    // 0) weights -> fp16 (+ Wo residual)
    wconv_kernel<<<(HID * HID) / 256, 256>>>(Wq, Wk, Wv, Wo);

    // 1) fused Q/K/V projection
    hgemm_qkv_kernel<<<dim3(HID / 64, MTOT / 64, 3), 128>>>(query, key_value, bq, bk, bv);

    // 2) flash attention partials (KV-split)
    const int attn_smem = (BM * KST + 4 * BN * KST) * 2 + 2 * BN * 4;  // 55808 B
    cudaFuncSetAttribute(attn_hmma_kernel, cudaFuncAttributeMaxDynamicSharedMemorySize, attn_smem);
    attn_hmma_kernel<<<dim3(NQL / BM, BATCH * NH, KVSPLIT), 128, attn_smem>>>(kv_mask);

    // 3) reduce partials -> fp16 g_AOh
    attn_reduce_kernel<<<(BATCH * NH * NQL * 16) / 256, 256>>>();

    // 4) output projection (2-pass W split, all-fp16 staging)
    const int smem_o = 6 * TILE * 2;   // 55296 B
    cudaFuncSetAttribute(hgemm_o_kernel, cudaFuncAttributeMaxDynamicSharedMemorySize, smem_o);
    hgemm_o_kernel<<<dim3(HID / 64, MTOT / 64), 128, smem_o>>>(bo, (float*)d_out);
}